// round 4
// baseline (speedup 1.0000x reference)
#include <cuda_runtime.h>
#include <math.h>

#define BB 8
#define NQ 900
#define DD 256
#define HH 8
#define HD 32
#define PP 4
#define BEV 200
#define FFN_D 512
#define M_ROWS (BB*NQ)   // 7200

// ---------------- consolidated scratch arena (no allocation) ----------------
// offsets (floats):
#define OFF_QIN   0
#define OFF_QKV   (OFF_QIN  + M_ROWS*DD)        // 7200*256
#define OFF_ATTN  (OFF_QKV  + M_ROWS*3*DD)
#define OFF_Q1    (OFF_ATTN + M_ROWS*DD)
#define OFF_Q2    (OFF_Q1   + M_ROWS*DD)
#define OFF_OFFS  (OFF_Q2   + M_ROWS*DD)
#define OFF_WT    (OFF_OFFS + M_ROWS*HH*PP*2)
#define OFF_FUS   (OFF_WT   + M_ROWS*HH*PP)
#define OFF_QU2   (OFF_FUS  + M_ROWS*DD)
#define OFF_Q3    (OFF_QU2  + M_ROWS*DD)
#define OFF_H1    (OFF_Q3   + M_ROWS*DD)
#define SCRATCH_TOTAL (OFF_H1 + M_ROWS*FFN_D)

__device__ float g_scratch[SCRATCH_TOTAL];

// ---------------- LayerNorm (optionally + pos) ----------------
__global__ void ln_kernel(const float* __restrict__ x, const float* __restrict__ pos,
                          const float* __restrict__ gam, const float* __restrict__ bet,
                          float* __restrict__ out)
{
    __shared__ float sb[8];
    __shared__ float stat;
    int r = blockIdx.x, t = threadIdx.x;
    int lane = t & 31, w = t >> 5;
    float v = x[r*DD + t];
    if (pos) v += pos[r*DD + t];

    float s = v;
    #pragma unroll
    for (int o = 16; o; o >>= 1) s += __shfl_xor_sync(0xffffffffu, s, o);
    if (lane == 0) sb[w] = s;
    __syncthreads();
    if (t == 0) { float tot = 0.f; for (int i = 0; i < 8; i++) tot += sb[i]; stat = tot * (1.0f/DD); }
    __syncthreads();
    float mean = stat;
    float c = v - mean;
    __syncthreads();
    s = c * c;
    #pragma unroll
    for (int o = 16; o; o >>= 1) s += __shfl_xor_sync(0xffffffffu, s, o);
    if (lane == 0) sb[w] = s;
    __syncthreads();
    if (t == 0) { float tot = 0.f; for (int i = 0; i < 8; i++) tot += sb[i]; stat = rsqrtf(tot * (1.0f/DD) + 1e-5f); }
    __syncthreads();
    out[r*DD + t] = c * stat * gam[t] + bet[t];
}

// ---------------- GEMM: C = A[M,K] * B[N,K]^T + bias (+res) (+act) ----------------
// act: 0 none, 1 relu, 2 tanh*scale
__global__ void gemm_nt(const float* __restrict__ A, const float* __restrict__ Bw,
                        const float* __restrict__ bias, const float* __restrict__ res,
                        float* __restrict__ C, int M, int N, int K, int act, float scale)
{
    __shared__ float As[16][136];   // 128 + pad8 (16B-aligned rows)
    __shared__ float Bs[16][72];    // 64 + pad8
    int bm = blockIdx.y * 128, bn = blockIdx.x * 64;
    int tid = threadIdx.x;
    int tx = tid & 15, ty = tid >> 4;
    float acc[8][4];
    #pragma unroll
    for (int i = 0; i < 8; i++)
        #pragma unroll
        for (int j = 0; j < 4; j++) acc[i][j] = 0.f;

    for (int k0 = 0; k0 < K; k0 += 16) {
        #pragma unroll
        for (int l = 0; l < 8; l++) {
            int i = tid + l * 256;
            int m = i >> 4, kk = i & 15;
            int gm = bm + m;
            As[kk][m] = (gm < M) ? A[(size_t)gm * K + k0 + kk] : 0.f;
        }
        #pragma unroll
        for (int l = 0; l < 4; l++) {
            int i = tid + l * 256;
            int n = i >> 4, kk = i & 15;
            int gn = bn + n;
            Bs[kk][n] = (gn < N) ? Bw[(size_t)gn * K + k0 + kk] : 0.f;
        }
        __syncthreads();
        #pragma unroll
        for (int kk = 0; kk < 16; kk++) {
            float4 a0 = *(const float4*)&As[kk][ty*8];
            float4 a1 = *(const float4*)&As[kk][ty*8 + 4];
            float4 b0 = *(const float4*)&Bs[kk][tx*4];
            float av[8] = {a0.x,a0.y,a0.z,a0.w,a1.x,a1.y,a1.z,a1.w};
            float bv[4] = {b0.x,b0.y,b0.z,b0.w};
            #pragma unroll
            for (int i = 0; i < 8; i++)
                #pragma unroll
                for (int j = 0; j < 4; j++)
                    acc[i][j] += av[i] * bv[j];
        }
        __syncthreads();
    }

    #pragma unroll
    for (int i = 0; i < 8; i++) {
        int gm = bm + ty*8 + i;
        if (gm >= M) continue;
        #pragma unroll
        for (int j = 0; j < 4; j++) {
            int gn = bn + tx*4 + j;
            if (gn >= N) continue;
            float v = acc[i][j] + bias[gn];
            if (act == 1) v = fmaxf(v, 0.f);
            else if (act == 2) v = tanhf(v) * scale;
            if (res) v += res[(size_t)gm * N + gn];
            C[(size_t)gm * N + gn] = v;
        }
    }
}

// ---------------- Multi-head self-attention ----------------
// grid: (ceil(NQ/8), H, B), block 256. qkv row layout: [q(256) | k(256) | v(256)]
__global__ void attn_kernel(const float* __restrict__ qkv, float* __restrict__ out)
{
    __shared__ float Qs[8][32];
    __shared__ float Ks[64][33];
    __shared__ float sc[8][NQ];
    __shared__ float inv_sum[8];

    int b = blockIdx.z, h = blockIdx.y;
    int q0 = blockIdx.x * 8;
    int tid = threadIdx.x;
    const float scale = 0.17677669529663687f; // 1/sqrt(32)

    for (int i = tid; i < 8*32; i += 256) {
        int q = i >> 5, d = i & 31;
        int gq = q0 + q;
        Qs[q][d] = (gq < NQ) ? qkv[(size_t)(b*NQ + gq)*768 + h*32 + d] : 0.f;
    }
    __syncthreads();

    // scores
    for (int k0 = 0; k0 < NQ; k0 += 64) {
        int kc = min(64, NQ - k0);
        for (int i = tid; i < 64*32; i += 256) {
            int k = i >> 5, d = i & 31;
            Ks[k][d] = (k < kc) ? qkv[(size_t)(b*NQ + k0 + k)*768 + 256 + h*32 + d] : 0.f;
        }
        __syncthreads();
        for (int i = tid; i < 8*64; i += 256) {
            int q = i >> 6, k = i & 63;
            if (k < kc) {
                float s = 0.f;
                #pragma unroll
                for (int d = 0; d < 32; d++) s += Qs[q][d] * Ks[k][d];
                sc[q][k0 + k] = s * scale;
            }
        }
        __syncthreads();
    }

    // softmax: warp w owns query w
    int w = tid >> 5, lane = tid & 31;
    {
        float m = -1e30f;
        for (int k = lane; k < NQ; k += 32) m = fmaxf(m, sc[w][k]);
        #pragma unroll
        for (int o = 16; o; o >>= 1) m = fmaxf(m, __shfl_xor_sync(0xffffffffu, m, o));
        float s = 0.f;
        for (int k = lane; k < NQ; k += 32) {
            float e = expf(sc[w][k] - m);
            sc[w][k] = e;
            s += e;
        }
        #pragma unroll
        for (int o = 16; o; o >>= 1) s += __shfl_xor_sync(0xffffffffu, s, o);
        if (lane == 0) inv_sum[w] = 1.f / s;
    }
    __syncthreads();

    // V phase: warp w handles keys k = w, w+8, ...; lane = d. V read straight from L2.
    float acc[8];
    #pragma unroll
    for (int q = 0; q < 8; q++) acc[q] = 0.f;
    int d = lane;
    for (int k = w; k < NQ; k += 8) {
        float v = qkv[(size_t)(b*NQ + k)*768 + 512 + h*32 + d];
        #pragma unroll
        for (int q = 0; q < 8; q++) acc[q] += sc[q][k] * v;
    }
    float* red = &Ks[0][0];   // reuse: 64*33 = 2112 floats >= 2048 needed
    __syncthreads();
    #pragma unroll
    for (int q = 0; q < 8; q++) red[(w*8 + q)*32 + d] = acc[q];
    __syncthreads();
    int q = w;
    float t = 0.f;
    #pragma unroll
    for (int ww = 0; ww < 8; ww++) t += red[(ww*8 + q)*32 + d];
    int gq = q0 + q;
    if (gq < NQ) out[(size_t)(b*NQ + gq)*DD + h*32 + d] = t * inv_sum[q];
}

// ---------------- softmax over P=4 groups (weights) ----------------
__global__ void softmax4_kernel(float* __restrict__ wt)
{
    int g = blockIdx.x * blockDim.x + threadIdx.x;
    if (g >= M_ROWS * HH) return;
    float* p = wt + (size_t)g * 4;
    float v0 = p[0], v1 = p[1], v2 = p[2], v3 = p[3];
    float m = fmaxf(fmaxf(v0, v1), fmaxf(v2, v3));
    float e0 = expf(v0 - m), e1 = expf(v1 - m), e2 = expf(v2 - m), e3 = expf(v3 - m);
    float inv = 1.f / (e0 + e1 + e2 + e3);
    p[0] = e0 * inv; p[1] = e1 * inv; p[2] = e2 * inv; p[3] = e3 * inv;
}

// ---------------- BEV bilinear sampling + weight fuse ----------------
// thread per (b,q,h,c): out[b][q][h*32+c] = sum_p wt * bilinear(memory)
__global__ void sample_kernel(const float* __restrict__ mem, const float* __restrict__ ref,
                              const float* __restrict__ off, const float* __restrict__ wt,
                              float* __restrict__ out)
{
    int idx = blockIdx.x * 256 + threadIdx.x;
    if (idx >= M_ROWS * DD) return;
    int c = idx & 31;
    int h = (idx >> 5) & 7;
    int row = idx >> 8;            // b*NQ + q
    int b = row / NQ;

    float rx = ref[row*2 + 0], ry = ref[row*2 + 1];
    const float* offr = off + (size_t)row*64 + h*8;
    const float* wtr  = wt  + (size_t)row*32 + h*4;
    const float* memb = mem + (size_t)b * (BEV*BEV) * DD + h*HD + c;

    float acc = 0.f;
    #pragma unroll
    for (int p = 0; p < PP; p++) {
        float gx = (rx + offr[p*2 + 0]) * (float)BEV - 0.5f;
        float gy = (ry + offr[p*2 + 1]) * (float)BEV - 0.5f;
        float x0f = floorf(gx), y0f = floorf(gy);
        int x0 = (int)x0f, y0 = (int)y0f;
        float wx1 = gx - x0f, wy1 = gy - y0f;
        float wx0 = 1.f - wx1, wy0 = 1.f - wy1;
        float v = 0.f;
        if ((unsigned)x0     < BEV && (unsigned)y0     < BEV) v += wx0*wy0 * memb[(size_t)(y0*BEV + x0    )*DD];
        if ((unsigned)(x0+1) < BEV && (unsigned)y0     < BEV) v += wx1*wy0 * memb[(size_t)(y0*BEV + x0 + 1)*DD];
        if ((unsigned)x0     < BEV && (unsigned)(y0+1) < BEV) v += wx0*wy1 * memb[(size_t)((y0+1)*BEV + x0    )*DD];
        if ((unsigned)(x0+1) < BEV && (unsigned)(y0+1) < BEV) v += wx1*wy1 * memb[(size_t)((y0+1)*BEV + x0 + 1)*DD];
        acc += wtr[p] * v;
    }
    out[idx] = acc;
}

// ---------------- launch ----------------
extern "C" void kernel_launch(void* const* d_in, const int* in_sizes, int n_in,
                              void* d_out, int out_size)
{
    const float* query   = (const float*)d_in[0];
    const float* memory  = (const float*)d_in[1];
    const float* refpts  = (const float*)d_in[2];
    const float* qpos    = (const float*)d_in[3];
    const float* in_w    = (const float*)d_in[4];
    const float* in_b    = (const float*)d_in[5];
    const float* out_w   = (const float*)d_in[6];
    const float* out_b   = (const float*)d_in[7];
    const float* off_w   = (const float*)d_in[8];
    const float* off_b   = (const float*)d_in[9];
    const float* wt_w    = (const float*)d_in[10];
    const float* wt_b    = (const float*)d_in[11];
    const float* co_w    = (const float*)d_in[12];
    const float* co_b    = (const float*)d_in[13];
    const float* f_w1    = (const float*)d_in[14];
    const float* f_b1    = (const float*)d_in[15];
    const float* f_w2    = (const float*)d_in[16];
    const float* f_b2    = (const float*)d_in[17];
    const float* n1s     = (const float*)d_in[18];
    const float* n1b     = (const float*)d_in[19];
    const float* n2s     = (const float*)d_in[20];
    const float* n2b     = (const float*)d_in[21];
    const float* n3s     = (const float*)d_in[22];
    const float* n3b     = (const float*)d_in[23];
    // d_in[24], d_in[25]: bev_h, bev_w (compile-time 200 for this problem)

    float* base = nullptr;
    cudaGetSymbolAddress((void**)&base, g_scratch);
    float* qin  = base + OFF_QIN;
    float* qkv  = base + OFF_QKV;
    float* attn = base + OFF_ATTN;
    float* q1   = base + OFF_Q1;
    float* q2   = base + OFF_Q2;
    float* off  = base + OFF_OFFS;
    float* wt   = base + OFF_WT;
    float* fus  = base + OFF_FUS;
    float* qu2  = base + OFF_QU2;
    float* q3   = base + OFF_Q3;
    float* h1   = base + OFF_H1;

    const int GY = (M_ROWS + 127) / 128;   // 57

    // 1) q_in = LN(query + pos; n1)
    ln_kernel<<<M_ROWS, 256>>>(query, qpos, n1s, n1b, qin);
    // 2) qkv = q_in @ in_w^T + in_b
    gemm_nt<<<dim3(12, GY), 256>>>(qin, in_w, in_b, nullptr, qkv, M_ROWS, 768, 256, 0, 0.f);
    // 3) self-attention
    attn_kernel<<<dim3((NQ + 7) / 8, HH, BB), 256>>>(qkv, attn);
    // 4) query1 = query + attn @ out_w^T + out_b
    gemm_nt<<<dim3(4, GY), 256>>>(attn, out_w, out_b, query, q1, M_ROWS, 256, 256, 0, 0.f);
    // 5) q2 = LN(query1 + pos; n2)
    ln_kernel<<<M_ROWS, 256>>>(q1, qpos, n2s, n2b, q2);
    // 6) offsets = tanh(q2 @ off_w^T + off_b) * RADIUS
    gemm_nt<<<dim3(1, GY), 256>>>(q2, off_w, off_b, nullptr, off, M_ROWS, 64, 256, 2, 0.2f);
    // 7) raw weights
    gemm_nt<<<dim3(1, GY), 256>>>(q2, wt_w, wt_b, nullptr, wt, M_ROWS, 32, 256, 0, 0.f);
    // 8) softmax over P
    softmax4_kernel<<<(M_ROWS * HH + 255) / 256, 256>>>(wt);
    // 9) bilinear sample + fuse
    sample_kernel<<<(M_ROWS * DD + 255) / 256, 256>>>(memory, refpts, off, wt, fus);
    // 10) query2 = query1 + fused @ co_w^T + co_b
    gemm_nt<<<dim3(4, GY), 256>>>(fus, co_w, co_b, q1, qu2, M_ROWS, 256, 256, 0, 0.f);
    // 11) q3 = LN(query2; n3)
    ln_kernel<<<M_ROWS, 256>>>(qu2, nullptr, n3s, n3b, q3);
    // 12) h1 = relu(q3 @ f_w1^T + f_b1)
    gemm_nt<<<dim3(8, GY), 256>>>(q3, f_w1, f_b1, nullptr, h1, M_ROWS, 512, 256, 1, 0.f);
    // 13) out = query2 + h1 @ f_w2^T + f_b2
    gemm_nt<<<dim3(4, GY), 256>>>(h1, f_w2, f_b2, qu2, (float*)d_out, M_ROWS, 256, 512, 0, 0.f);
}

// round 6
// speedup vs baseline: 1.5619x; 1.5619x over previous
#include <cuda_runtime.h>
#include <math.h>

#define BB 8
#define NQ 900
#define DD 256
#define HH 8
#define HD 32
#define PP 4
#define BEV 200
#define FFN_D 512
#define M_ROWS (BB*NQ)   // 7200

// ---------------- consolidated scratch arena (no allocation) ----------------
#define OFF_QIN   0
#define OFF_QKV   (OFF_QIN  + M_ROWS*DD)
#define OFF_ATTN  (OFF_QKV  + M_ROWS*3*DD)
#define OFF_Q1    (OFF_ATTN + M_ROWS*DD)
#define OFF_Q2    (OFF_Q1   + M_ROWS*DD)
#define OFF_OFFS  (OFF_Q2   + M_ROWS*DD)
#define OFF_WT    (OFF_OFFS + M_ROWS*HH*PP*2)
#define OFF_FUS   (OFF_WT   + M_ROWS*HH*PP)
#define OFF_QU2   (OFF_FUS  + M_ROWS*DD)
#define OFF_Q3    (OFF_QU2  + M_ROWS*DD)
#define OFF_H1    (OFF_Q3   + M_ROWS*DD)
#define SCRATCH_TOTAL (OFF_H1 + M_ROWS*FFN_D)

__device__ float g_scratch[SCRATCH_TOTAL];

// ---------------- LayerNorm (optionally + pos) ----------------
__global__ void ln_kernel(const float* __restrict__ x, const float* __restrict__ pos,
                          const float* __restrict__ gam, const float* __restrict__ bet,
                          float* __restrict__ out)
{
    __shared__ float sb[8];
    __shared__ float stat;
    int r = blockIdx.x, t = threadIdx.x;
    int lane = t & 31, w = t >> 5;
    float v = x[r*DD + t];
    if (pos) v += pos[r*DD + t];

    float s = v;
    #pragma unroll
    for (int o = 16; o; o >>= 1) s += __shfl_xor_sync(0xffffffffu, s, o);
    if (lane == 0) sb[w] = s;
    __syncthreads();
    if (t == 0) { float tot = 0.f; for (int i = 0; i < 8; i++) tot += sb[i]; stat = tot * (1.0f/DD); }
    __syncthreads();
    float mean = stat;
    float c = v - mean;
    __syncthreads();
    s = c * c;
    #pragma unroll
    for (int o = 16; o; o >>= 1) s += __shfl_xor_sync(0xffffffffu, s, o);
    if (lane == 0) sb[w] = s;
    __syncthreads();
    if (t == 0) { float tot = 0.f; for (int i = 0; i < 8; i++) tot += sb[i]; stat = rsqrtf(tot * (1.0f/DD) + 1e-5f); }
    __syncthreads();
    out[r*DD + t] = c * stat * gam[t] + bet[t];
}

// ---------------- GEMM: C = A[M,K] * B[N,K]^T + bias (+res) (+act) ----------------
// 128x64 tile, BK=16, float4 gmem loads, double-buffered smem, 1 sync/iter.
// act: 0 none, 1 relu, 2 tanh*scale
__global__ __launch_bounds__(256, 2)
void gemm_nt(const float* __restrict__ A, const float* __restrict__ Bw,
             const float* __restrict__ bias, const float* __restrict__ res,
             float* __restrict__ C, int M, int N, int K, int act, float scale)
{
    __shared__ float As[2][16][136];
    __shared__ float Bs[2][16][72];
    int bm = blockIdx.y * 128, bn = blockIdx.x * 64;
    int tid = threadIdx.x;
    int tx = tid & 15, ty = tid >> 4;

    // load roles
    int am = tid >> 1, ak = (tid & 1) * 8;      // A: 128 rows x 2 float4
    int bnr = tid >> 2, bk = (tid & 3) * 4;     // B: 64 rows x 1 float4
    int gmA = bm + am;  bool va = (gmA < M);
    int gnB = bn + bnr; bool vb = (gnB < N);
    const float* Ap = A  + (size_t)(va ? gmA : 0) * K + ak;
    const float* Bp = Bw + (size_t)(vb ? gnB : 0) * K + bk;

    const float4 fz = make_float4(0.f, 0.f, 0.f, 0.f);
    float4 a0 = va ? *(const float4*)(Ap)     : fz;
    float4 a1 = va ? *(const float4*)(Ap + 4) : fz;
    float4 b0 = vb ? *(const float4*)(Bp)     : fz;

    float acc[8][4];
    #pragma unroll
    for (int i = 0; i < 8; i++)
        #pragma unroll
        for (int j = 0; j < 4; j++) acc[i][j] = 0.f;

    // prime buffer 0
    As[0][ak+0][am] = a0.x; As[0][ak+1][am] = a0.y; As[0][ak+2][am] = a0.z; As[0][ak+3][am] = a0.w;
    As[0][ak+4][am] = a1.x; As[0][ak+5][am] = a1.y; As[0][ak+6][am] = a1.z; As[0][ak+7][am] = a1.w;
    Bs[0][bk+0][bnr] = b0.x; Bs[0][bk+1][bnr] = b0.y; Bs[0][bk+2][bnr] = b0.z; Bs[0][bk+3][bnr] = b0.w;
    __syncthreads();

    int nt = K >> 4;
    for (int t = 0; t < nt; t++) {
        int buf = t & 1;
        bool more = (t + 1 < nt);
        if (more) {
            const float* Ap2 = Ap + (t + 1) * 16;
            const float* Bp2 = Bp + (t + 1) * 16;
            a0 = va ? *(const float4*)(Ap2)     : fz;
            a1 = va ? *(const float4*)(Ap2 + 4) : fz;
            b0 = vb ? *(const float4*)(Bp2)     : fz;
        }
        #pragma unroll
        for (int kk = 0; kk < 16; kk++) {
            float4 x0 = *(const float4*)&As[buf][kk][ty*8];
            float4 x1 = *(const float4*)&As[buf][kk][ty*8 + 4];
            float4 y0 = *(const float4*)&Bs[buf][kk][tx*4];
            float av[8] = {x0.x,x0.y,x0.z,x0.w,x1.x,x1.y,x1.z,x1.w};
            float bv[4] = {y0.x,y0.y,y0.z,y0.w};
            #pragma unroll
            for (int i = 0; i < 8; i++)
                #pragma unroll
                for (int j = 0; j < 4; j++)
                    acc[i][j] += av[i] * bv[j];
        }
        if (more) {
            int nb = buf ^ 1;
            As[nb][ak+0][am] = a0.x; As[nb][ak+1][am] = a0.y; As[nb][ak+2][am] = a0.z; As[nb][ak+3][am] = a0.w;
            As[nb][ak+4][am] = a1.x; As[nb][ak+5][am] = a1.y; As[nb][ak+6][am] = a1.z; As[nb][ak+7][am] = a1.w;
            Bs[nb][bk+0][bnr] = b0.x; Bs[nb][bk+1][bnr] = b0.y; Bs[nb][bk+2][bnr] = b0.z; Bs[nb][bk+3][bnr] = b0.w;
        }
        __syncthreads();
    }

    // epilogue
    bool vecN = (bn + 64 <= N);
    #pragma unroll
    for (int i = 0; i < 8; i++) {
        int gm = bm + ty*8 + i;
        if (gm >= M) continue;
        int gn0 = bn + tx*4;
        if (vecN) {
            float4 bia = *(const float4*)(bias + gn0);
            float4 v = make_float4(acc[i][0] + bia.x, acc[i][1] + bia.y,
                                   acc[i][2] + bia.z, acc[i][3] + bia.w);
            if (act == 1) {
                v.x = fmaxf(v.x, 0.f); v.y = fmaxf(v.y, 0.f);
                v.z = fmaxf(v.z, 0.f); v.w = fmaxf(v.w, 0.f);
            } else if (act == 2) {
                v.x = tanhf(v.x)*scale; v.y = tanhf(v.y)*scale;
                v.z = tanhf(v.z)*scale; v.w = tanhf(v.w)*scale;
            }
            if (res) {
                float4 r = *(const float4*)(res + (size_t)gm*N + gn0);
                v.x += r.x; v.y += r.y; v.z += r.z; v.w += r.w;
            }
            *(float4*)(C + (size_t)gm*N + gn0) = v;
        } else {
            #pragma unroll
            for (int j = 0; j < 4; j++) {
                int gn = gn0 + j;
                if (gn >= N) continue;
                float v = acc[i][j] + bias[gn];
                if (act == 1) v = fmaxf(v, 0.f);
                else if (act == 2) v = tanhf(v) * scale;
                if (res) v += res[(size_t)gm * N + gn];
                C[(size_t)gm * N + gn] = v;
            }
        }
    }
}

// ---------------- Flash-style multi-head self-attention ----------------
// grid (15, 8, 8), block 256. q-tile 64, k-chunk 128, online softmax.
// dyn smem layout (floats): Qs [32][68] @0; Ks [32][132] @2176; Ps(128 rows,
// stride 100, swizzle ((k>>2)&7)*4) @6400; Lsm[64] @19200. total 19264 f = 77056 B.
#define ATT_SMEM_BYTES (19264*4)

__global__ __launch_bounds__(256, 2)
void attn_kernel(const float* __restrict__ qkv, float* __restrict__ out)
{
    extern __shared__ float sm[];
    float* Qs  = sm;            // [d][q] : 32 x 68
    float* Ks  = sm + 2176;     // [d][k] : 32 x 132
    float* Ps  = sm + 6400;     // [k][q] swizzled, stride 100
    float* Lsm = sm + 19200;    // [64]

    int b = blockIdx.z, h = blockIdx.y;
    int q0 = blockIdx.x * 64;
    int tid = threadIdx.x;
    int tx = tid & 31, ty = tid >> 5;
    const float SCALE = 0.17677669529663687f;

    // ---- load Q tile -> Qs[d][q] (transposed) ----
    {
        int q = tid >> 2, dg = tid & 3;
        int gq = q0 + q;
        const float* src = qkv + (size_t)(b*NQ + (gq < NQ ? gq : 0))*768 + h*32 + dg*8;
        float4 x0 = make_float4(0,0,0,0), x1 = x0;
        if (gq < NQ) { x0 = *(const float4*)src; x1 = *(const float4*)(src + 4); }
        int d = dg * 8;
        Qs[(d+0)*68 + q] = x0.x; Qs[(d+1)*68 + q] = x0.y;
        Qs[(d+2)*68 + q] = x0.z; Qs[(d+3)*68 + q] = x0.w;
        Qs[(d+4)*68 + q] = x1.x; Qs[(d+5)*68 + q] = x1.y;
        Qs[(d+6)*68 + q] = x1.z; Qs[(d+7)*68 + q] = x1.w;
    }

    float o[8][4];
    float m[8], l[8];
    #pragma unroll
    for (int i = 0; i < 8; i++) {
        m[i] = -1e30f; l[i] = 0.f;
        #pragma unroll
        for (int j = 0; j < 4; j++) o[i][j] = 0.f;
    }

    int kg = tx >> 3, dgi = tx & 7;   // O-phase roles: k group / d group

    for (int c = 0; c < 8; c++) {
        int kc0 = c * 128;

        // ---- load K chunk -> Ks[d][k] (transposed) ----
        {
            int k = tid >> 1, dg = tid & 1;
            int kglob = kc0 + k;
            const float* src = qkv + (size_t)(b*NQ + (kglob < NQ ? kglob : 0))*768 + 256 + h*32 + dg*16;
            float4 x0 = make_float4(0,0,0,0), x1 = x0, x2 = x0, x3 = x0;
            if (kglob < NQ) {
                x0 = *(const float4*)(src);      x1 = *(const float4*)(src + 4);
                x2 = *(const float4*)(src + 8);  x3 = *(const float4*)(src + 12);
            }
            int d = dg * 16;
            Ks[(d+ 0)*132 + k] = x0.x; Ks[(d+ 1)*132 + k] = x0.y;
            Ks[(d+ 2)*132 + k] = x0.z; Ks[(d+ 3)*132 + k] = x0.w;
            Ks[(d+ 4)*132 + k] = x1.x; Ks[(d+ 5)*132 + k] = x1.y;
            Ks[(d+ 6)*132 + k] = x1.z; Ks[(d+ 7)*132 + k] = x1.w;
            Ks[(d+ 8)*132 + k] = x2.x; Ks[(d+ 9)*132 + k] = x2.y;
            Ks[(d+10)*132 + k] = x2.z; Ks[(d+11)*132 + k] = x2.w;
            Ks[(d+12)*132 + k] = x3.x; Ks[(d+13)*132 + k] = x3.y;
            Ks[(d+14)*132 + k] = x3.z; Ks[(d+15)*132 + k] = x3.w;
        }
        __syncthreads();   // Ks ready; previous O-phase done reading Ps

        // ---- S = Q K^T  (thread tile: 8 q x 4 k) ----
        float acc[8][4];
        #pragma unroll
        for (int i = 0; i < 8; i++)
            #pragma unroll
            for (int j = 0; j < 4; j++) acc[i][j] = 0.f;

        #pragma unroll 8
        for (int d = 0; d < 32; d++) {
            const float4* Q4 = (const float4*)(Qs + d*68);
            float4 qa = Q4[ty*2], qb = Q4[ty*2 + 1];
            float4 kv = ((const float4*)(Ks + d*132))[tx];
            float qq[8] = {qa.x,qa.y,qa.z,qa.w,qb.x,qb.y,qb.z,qb.w};
            #pragma unroll
            for (int i = 0; i < 8; i++) {
                acc[i][0] += qq[i] * kv.x;
                acc[i][1] += qq[i] * kv.y;
                acc[i][2] += qq[i] * kv.z;
                acc[i][3] += qq[i] * kv.w;
            }
        }

        // scale + mask
        #pragma unroll
        for (int j = 0; j < 4; j++) {
            bool vk = (kc0 + tx*4 + j) < NQ;
            #pragma unroll
            for (int i = 0; i < 8; i++)
                acc[i][j] = vk ? acc[i][j]*SCALE : -1e30f;
        }

        // online softmax per q row (row = warp ty, all 32 lanes hold its k slices)
        #pragma unroll
        for (int i = 0; i < 8; i++) {
            float rm = fmaxf(fmaxf(acc[i][0], acc[i][1]), fmaxf(acc[i][2], acc[i][3]));
            #pragma unroll
            for (int off = 16; off; off >>= 1) rm = fmaxf(rm, __shfl_xor_sync(0xffffffffu, rm, off));
            float mn = fmaxf(m[i], rm);
            float alpha = __expf(m[i] - mn);
            m[i] = mn;
            float ls = 0.f;
            #pragma unroll
            for (int j = 0; j < 4; j++) {
                float p = __expf(acc[i][j] - mn);
                acc[i][j] = p;
                ls += p;
            }
            #pragma unroll
            for (int off = 16; off; off >>= 1) ls += __shfl_xor_sync(0xffffffffu, ls, off);
            l[i] = l[i]*alpha + ls;
            #pragma unroll
            for (int j = 0; j < 4; j++) o[i][j] *= alpha;
        }

        // store P -> Ps[k][q] (stride 100, swizzle ((k>>2)&7)*4 = (tx&7)*4)
        {
            int sw = (tx & 7) * 4;
            #pragma unroll
            for (int j = 0; j < 4; j++) {
                float* dst = Ps + (tx*4 + j)*100 + sw + ty*8;
                *(float4*)(dst)     = make_float4(acc[0][j], acc[1][j], acc[2][j], acc[3][j]);
                *(float4*)(dst + 4) = make_float4(acc[4][j], acc[5][j], acc[6][j], acc[7][j]);
            }
        }
        __syncthreads();   // Ps ready; all S-phase Ks reads done

        // ---- O += P V  (thread: 8 q x 4 d, k split 4-way over kg) ----
        {
            int d0 = dgi * 4;
            const float* vbase = qkv + (size_t)(b*NQ)*768 + 512 + h*32 + d0;
            #pragma unroll 4
            for (int i2 = 0; i2 < 32; i2++) {
                int k = 4*i2 + kg;
                int kglob = kc0 + k;
                const float* prow = Ps + k*100 + (i2 & 7)*4;
                float4 pa = *(const float4*)(prow + ty*8);
                float4 pb = *(const float4*)(prow + ty*8 + 4);
                float4 v = make_float4(0,0,0,0);
                if (kglob < NQ) v = *(const float4*)(vbase + (size_t)kglob*768);
                float pv[8] = {pa.x,pa.y,pa.z,pa.w,pb.x,pb.y,pb.z,pb.w};
                #pragma unroll
                for (int i = 0; i < 8; i++) {
                    o[i][0] += pv[i] * v.x;
                    o[i][1] += pv[i] * v.y;
                    o[i][2] += pv[i] * v.z;
                    o[i][3] += pv[i] * v.w;
                }
            }
        }
        // next chunk's first sync protects Ps before overwrite
    }

    __syncthreads();
    // ---- reduce 4 kg partials via smem (reuse Ps area) ----
    float* red = Ps;
    #pragma unroll
    for (int i = 0; i < 8; i++) {
        float* dst = red + kg*2048 + (ty*8 + i)*32 + dgi*4;
        *(float4*)dst = make_float4(o[i][0], o[i][1], o[i][2], o[i][3]);
    }
    if (tx == 0) {
        #pragma unroll
        for (int i = 0; i < 8; i++) Lsm[ty*8 + i] = l[i];
    }
    __syncthreads();

    {
        int q = tid >> 2, dgrp = tid & 3;
        int gq = q0 + q;
        if (gq < NQ) {
            int d = dgrp * 8;
            float s0 = 0, s1 = 0, s2 = 0, s3 = 0, s4 = 0, s5 = 0, s6 = 0, s7 = 0;
            #pragma unroll
            for (int g = 0; g < 4; g++) {
                const float* src = red + g*2048 + q*32 + d;
                float4 u = *(const float4*)(src);
                float4 w = *(const float4*)(src + 4);
                s0 += u.x; s1 += u.y; s2 += u.z; s3 += u.w;
                s4 += w.x; s5 += w.y; s6 += w.z; s7 += w.w;
            }
            float linv = 1.f / Lsm[q];
            float* dst = out + (size_t)(b*NQ + gq)*DD + h*32 + d;
            *(float4*)(dst)     = make_float4(s0*linv, s1*linv, s2*linv, s3*linv);
            *(float4*)(dst + 4) = make_float4(s4*linv, s5*linv, s6*linv, s7*linv);
        }
    }
}

// ---------------- BEV bilinear sampling + inline weight softmax + fuse ----------------
__global__ void sample_kernel(const float* __restrict__ mem, const float* __restrict__ ref,
                              const float* __restrict__ off, const float* __restrict__ wt,
                              float* __restrict__ out)
{
    int idx = blockIdx.x * 256 + threadIdx.x;
    if (idx >= M_ROWS * DD) return;
    int c = idx & 31;
    int h = (idx >> 5) & 7;
    int row = idx >> 8;            // b*NQ + q
    int b = row / NQ;

    float rx = ref[row*2 + 0], ry = ref[row*2 + 1];
    const float* offr = off + (size_t)row*64 + h*8;
    const float* wtr  = wt  + (size_t)row*32 + h*4;
    const float* memb = mem + (size_t)b * (BEV*BEV) * DD + h*HD + c;

    // inline softmax over P=4
    float w0 = wtr[0], w1 = wtr[1], w2 = wtr[2], w3 = wtr[3];
    float wm = fmaxf(fmaxf(w0, w1), fmaxf(w2, w3));
    float e0 = __expf(w0 - wm), e1 = __expf(w1 - wm), e2 = __expf(w2 - wm), e3 = __expf(w3 - wm);
    float winv = 1.f / (e0 + e1 + e2 + e3);
    float wsm[4] = {e0*winv, e1*winv, e2*winv, e3*winv};

    float acc = 0.f;
    #pragma unroll
    for (int p = 0; p < PP; p++) {
        float gx = (rx + offr[p*2 + 0]) * (float)BEV - 0.5f;
        float gy = (ry + offr[p*2 + 1]) * (float)BEV - 0.5f;
        float x0f = floorf(gx), y0f = floorf(gy);
        int x0 = (int)x0f, y0 = (int)y0f;
        float wx1 = gx - x0f, wy1 = gy - y0f;
        float wx0 = 1.f - wx1, wy0 = 1.f - wy1;
        float v = 0.f;
        if ((unsigned)x0     < BEV && (unsigned)y0     < BEV) v += wx0*wy0 * memb[(size_t)(y0*BEV + x0    )*DD];
        if ((unsigned)(x0+1) < BEV && (unsigned)y0     < BEV) v += wx1*wy0 * memb[(size_t)(y0*BEV + x0 + 1)*DD];
        if ((unsigned)x0     < BEV && (unsigned)(y0+1) < BEV) v += wx0*wy1 * memb[(size_t)((y0+1)*BEV + x0    )*DD];
        if ((unsigned)(x0+1) < BEV && (unsigned)(y0+1) < BEV) v += wx1*wy1 * memb[(size_t)((y0+1)*BEV + x0 + 1)*DD];
        acc += wsm[p] * v;
    }
    out[idx] = acc;
}

// ---------------- launch ----------------
extern "C" void kernel_launch(void* const* d_in, const int* in_sizes, int n_in,
                              void* d_out, int out_size)
{
    const float* query   = (const float*)d_in[0];
    const float* memory  = (const float*)d_in[1];
    const float* refpts  = (const float*)d_in[2];
    const float* qpos    = (const float*)d_in[3];
    const float* in_w    = (const float*)d_in[4];
    const float* in_b    = (const float*)d_in[5];
    const float* out_w   = (const float*)d_in[6];
    const float* out_b   = (const float*)d_in[7];
    const float* off_w   = (const float*)d_in[8];
    const float* off_b   = (const float*)d_in[9];
    const float* wt_w    = (const float*)d_in[10];
    const float* wt_b    = (const float*)d_in[11];
    const float* co_w    = (const float*)d_in[12];
    const float* co_b    = (const float*)d_in[13];
    const float* f_w1    = (const float*)d_in[14];
    const float* f_b1    = (const float*)d_in[15];
    const float* f_w2    = (const float*)d_in[16];
    const float* f_b2    = (const float*)d_in[17];
    const float* n1s     = (const float*)d_in[18];
    const float* n1b     = (const float*)d_in[19];
    const float* n2s     = (const float*)d_in[20];
    const float* n2b     = (const float*)d_in[21];
    const float* n3s     = (const float*)d_in[22];
    const float* n3b     = (const float*)d_in[23];

    float* base = nullptr;
    cudaGetSymbolAddress((void**)&base, g_scratch);
    float* qin  = base + OFF_QIN;
    float* qkv  = base + OFF_QKV;
    float* attn = base + OFF_ATTN;
    float* q1   = base + OFF_Q1;
    float* q2   = base + OFF_Q2;
    float* off  = base + OFF_OFFS;
    float* wt   = base + OFF_WT;
    float* fus  = base + OFF_FUS;
    float* qu2  = base + OFF_QU2;
    float* q3   = base + OFF_Q3;
    float* h1   = base + OFF_H1;

    cudaFuncSetAttribute(attn_kernel, cudaFuncAttributeMaxDynamicSharedMemorySize, ATT_SMEM_BYTES);

    const int GY = (M_ROWS + 127) / 128;   // 57

    // 1) q_in = LN(query + pos; n1)
    ln_kernel<<<M_ROWS, 256>>>(query, qpos, n1s, n1b, qin);
    // 2) qkv = q_in @ in_w^T + in_b
    gemm_nt<<<dim3(12, GY), 256>>>(qin, in_w, in_b, nullptr, qkv, M_ROWS, 768, 256, 0, 0.f);
    // 3) self-attention (flash)
    attn_kernel<<<dim3((NQ + 63) / 64, HH, BB), 256, ATT_SMEM_BYTES>>>(qkv, attn);
    // 4) query1 = query + attn @ out_w^T + out_b
    gemm_nt<<<dim3(4, GY), 256>>>(attn, out_w, out_b, query, q1, M_ROWS, 256, 256, 0, 0.f);
    // 5) q2 = LN(query1 + pos; n2)
    ln_kernel<<<M_ROWS, 256>>>(q1, qpos, n2s, n2b, q2);
    // 6) offsets = tanh(q2 @ off_w^T + off_b) * RADIUS
    gemm_nt<<<dim3(1, GY), 256>>>(q2, off_w, off_b, nullptr, off, M_ROWS, 64, 256, 2, 0.2f);
    // 7) raw weights (softmax fused into sample_kernel)
    gemm_nt<<<dim3(1, GY), 256>>>(q2, wt_w, wt_b, nullptr, wt, M_ROWS, 32, 256, 0, 0.f);
    // 8) bilinear sample + softmax + fuse
    sample_kernel<<<(M_ROWS * DD + 255) / 256, 256>>>(memory, refpts, off, wt, fus);
    // 9) query2 = query1 + fused @ co_w^T + co_b
    gemm_nt<<<dim3(4, GY), 256>>>(fus, co_w, co_b, q1, qu2, M_ROWS, 256, 256, 0, 0.f);
    // 10) q3 = LN(query2; n3)
    ln_kernel<<<M_ROWS, 256>>>(qu2, nullptr, n3s, n3b, q3);
    // 11) h1 = relu(q3 @ f_w1^T + f_b1)
    gemm_nt<<<dim3(8, GY), 256>>>(q3, f_w1, f_b1, nullptr, h1, M_ROWS, 512, 256, 1, 0.f);
    // 12) out = query2 + h1 @ f_w2^T + f_b2
    gemm_nt<<<dim3(4, GY), 256>>>(h1, f_w2, f_b2, qu2, (float*)d_out, M_ROWS, 256, 512, 0, 0.f);
}